// round 13
// baseline (speedup 1.0000x reference)
#include <cuda_runtime.h>
#include <cstdint>

#define BB 16
#define NN 2048
#define NCLS 21
#define NTHREADS 1024
#define NMS_THR 0.3f

#define MAXC 384          // max boxes per class (mean ~98; huge safety margin)
#define MWORDS 12         // 384 bits of suppression mask per row
#define K2_THREADS 512
#define K2_WARPS 16

// ---- global scratch (static __device__; no allocation) ----
__device__ float4         g_obox[BB * NN];   // class-compacted offset xyxy
__device__ float4         g_boxc[BB * NN];   // class-compacted ORIGINAL xywh box
__device__ float          g_scc [BB * NN];   // class-compacted score
__device__ unsigned short g_rank[BB * NN];   // sorted-rank per compacted entry
__device__ int            g_base[BB * 32];
__device__ int            g_cnt [BB * 32];

// ---- K1 dynamic shared memory layout (bytes); hist double-buffered ----
#define OFF_KEYSA  0        // uint  [2048]   8192
#define OFF_KEYSB  8192     // uint  [2048]   8192
#define OFF_HISTA  16384    // ushort[256*64] 32768   (hist[d*64+v])
#define OFF_HISTB  49152    // ushort[256*64] 32768
#define OFF_IDXA   81920    // ushort[2048]   4096
#define OFF_IDXB   86016    // ushort[2048]   4096
#define OFF_CLS    90112    // uchar [2048]   2048
#define OFF_DTOT   92160    // uint  [256]    1024
#define OFF_BASES  93184    // int   [64]      256
#define OFF_MAXB   93440    // int               4
#define SMEM_BYTES 94208

// PDL primitives (sm_90+)
__device__ __forceinline__ void pdl_launch_dependents() {
    asm volatile("griddepcontrol.launch_dependents;");
}
__device__ __forceinline__ void pdl_wait() {
    asm volatile("griddepcontrol.wait;");
}

// ============================================================================
// K1: per-batch stable sort by descending score + per-class compaction + copies
// ============================================================================
__global__ __launch_bounds__(NTHREADS) void k1_sort_kernel(
    const float* __restrict__ enc_cls,
    const float* __restrict__ enc_reg,
    const float* __restrict__ boxes,
    const float* __restrict__ scores,
    const int*   __restrict__ classes,
    float* __restrict__ out)
{
    const int tid = threadIdx.x;

    if (blockIdx.x >= BB) {
        // ---- copy blocks: pass-through of encoded_cls/encoded_reg
        const int cb  = blockIdx.x - BB;
        const int ncb = gridDim.x - BB;
        const int nClsV = (BB * NN * NCLS) / 4;
        const int nRegV = (BB * NN * 4) / 4;
        const float4* s1 = (const float4*)enc_cls;
        const float4* s2 = (const float4*)enc_reg;
        float4* d1 = (float4*)out;
        float4* d2 = (float4*)(out + (size_t)BB * NN * NCLS);
        for (int i = cb * NTHREADS + tid; i < nClsV; i += ncb * NTHREADS) d1[i] = s1[i];
        for (int i = cb * NTHREADS + tid; i < nRegV; i += ncb * NTHREADS) d2[i] = s2[i];
        pdl_launch_dependents();
        return;
    }

    extern __shared__ char smem[];
    unsigned*       keysA = (unsigned*)      (smem + OFF_KEYSA);
    unsigned*       keysB = (unsigned*)      (smem + OFF_KEYSB);
    unsigned short* histA = (unsigned short*)(smem + OFF_HISTA);
    unsigned short* histB = (unsigned short*)(smem + OFF_HISTB);
    unsigned short* idxA  = (unsigned short*)(smem + OFF_IDXA);
    unsigned short* idxB  = (unsigned short*)(smem + OFF_IDXB);
    unsigned char*  clsR  = (unsigned char*) (smem + OFF_CLS);
    unsigned*       dtot  = (unsigned*)      (smem + OFF_DTOT);
    int*            cnts  = (int*)           (smem + OFF_BASES);
    int*            bases = (int*)           (smem + OFF_BASES) + 32;
    int*            maxb  = (int*)           (smem + OFF_MAXB);

    const int b = blockIdx.x;
    const float4* bx4 = (const float4*)(boxes + (size_t)b * NN * 4);
    const float*  sc  = scores  + (size_t)b * NN;
    const int*    cl  = classes + (size_t)b * NN;

    const int lane   = tid & 31;
    const int warpId = tid >> 5;
    const unsigned ltmask = (1u << lane) - 1u;

    if (tid == 0) *maxb = 0;

    // up-front zero of histA (pass 0's buffer)
    {
        uint4* h4 = (uint4*)histA;
        #pragma unroll
        for (int i = tid; i < 2048; i += NTHREADS) h4[i] = make_uint4(0, 0, 0, 0);
    }
    __syncthreads();

    // ---- 1) keys (descending score, stable) + max coord reduce
    int localmax = 0;
    #pragma unroll
    for (int e = tid; e < NN; e += NTHREADS) {
        keysA[e] = ~__float_as_uint(sc[e]);
        idxA[e]  = (unsigned short)e;
        float4 bbx = bx4[e];
        float x2 = bbx.x + bbx.z, y2 = bbx.y + bbx.w;
        float m = fmaxf(fmaxf(bbx.x, bbx.y), fmaxf(x2, y2));
        localmax = max(localmax, __float_as_int(m));
    }
    atomicMax(maxb, localmax);
    __syncthreads();

    // ---- 2) stable LSD radix: 4 x 8-bit, 64 warp-chunks of 32
    // hist double-buffered: next pass's buffer is zeroed by warps 16..31
    // during the scan-256 window (where they were idle).
    const int v0 = warpId, v1 = warpId + 32;
    #pragma unroll
    for (int pass = 0; pass < 4; pass++) {
        const unsigned sh = pass * 8;
        const unsigned*       kin  = (pass & 1) ? keysB : keysA;
        unsigned*             kout = (pass & 1) ? keysA : keysB;
        const unsigned short* iin  = (pass & 1) ? idxB  : idxA;
        unsigned short*       iout = (pass & 1) ? idxA  : idxB;
        unsigned short*       hist  = (pass & 1) ? histB : histA;
        unsigned short*       hnext = (pass & 1) ? histA : histB;

        unsigned k0 = kin[tid], k1 = kin[tid + 1024];
        unsigned d0 = (k0 >> sh) & 255u, d1 = (k1 >> sh) & 255u;
        unsigned m0 = __match_any_sync(0xffffffffu, d0);
        unsigned r0 = __popc(m0 & ltmask);
        if (r0 == 0) hist[d0 * 64 + v0] = (unsigned short)__popc(m0);
        unsigned m1 = __match_any_sync(0xffffffffu, d1);
        unsigned r1 = __popc(m1 & ltmask);
        if (r1 == 0) hist[d1 * 64 + v1] = (unsigned short)__popc(m1);
        __syncthreads();

        // per-digit exclusive scan over 64 chunks: warp w scans digits [8w,8w+8)
        #pragma unroll
        for (int j = 0; j < 8; j++) {
            const int d = warpId * 8 + j;
            unsigned a  = hist[d * 64 + 2 * lane];
            unsigned b2 = hist[d * 64 + 2 * lane + 1];
            unsigned s = a + b2;
            unsigned incl = s;
            #pragma unroll
            for (int o = 1; o < 32; o <<= 1) {
                unsigned t = __shfl_up_sync(0xffffffffu, incl, o);
                if (lane >= o) incl += t;
            }
            unsigned excl = incl - s;
            hist[d * 64 + 2 * lane]     = (unsigned short)excl;
            hist[d * 64 + 2 * lane + 1] = (unsigned short)(excl + a);
            if (lane == 31) dtot[d] = incl;
        }
        __syncthreads();

        // warp 0: exclusive scan of 256 digit totals; warps 16..31: zero hnext
        if (tid < 32) {
            unsigned s[8], lsum = 0;
            #pragma unroll
            for (int j = 0; j < 8; j++) { s[j] = dtot[tid * 8 + j]; lsum += s[j]; }
            unsigned tot = lsum;
            #pragma unroll
            for (int o = 1; o < 32; o <<= 1) {
                unsigned t = __shfl_up_sync(0xffffffffu, lsum, o);
                if (lane >= o) lsum += t;
            }
            unsigned run = lsum - tot;
            #pragma unroll
            for (int j = 0; j < 8; j++) { unsigned t = s[j]; dtot[tid * 8 + j] = run; run += t; }
        } else if (tid >= 512 && pass < 3) {
            uint4* h4 = (uint4*)hnext;
            #pragma unroll
            for (int i = tid - 512; i < 2048; i += 512) h4[i] = make_uint4(0, 0, 0, 0);
        }
        __syncthreads();

        unsigned dst0 = dtot[d0] + hist[d0 * 64 + v0] + r0;
        kout[dst0] = k0; iout[dst0] = iin[tid];
        unsigned dst1 = dtot[d1] + hist[d1 * 64 + v1] + r1;
        kout[dst1] = k1; iout[dst1] = iin[tid + 1024];
        __syncthreads();
    }
    // final order in idxA; final sorted keys in keysA (score bits = ~key)

    // ---- 3) classes by sorted rank
    #pragma unroll
    for (int r = tid; r < NN; r += NTHREADS)
        clsR[r] = (unsigned char)cl[idxA[r]];
    __syncthreads();

    // ---- 4) per-class compaction -> global (warp c owns class c)
    const float m1v = __int_as_float(*maxb) + 1.0f;

    if (warpId < NCLS) {
        int cnt = 0;
        for (int r0i = 0; r0i < NN; r0i += 32) {
            bool f = (clsR[r0i + lane] == (unsigned char)warpId);
            cnt += __popc(__ballot_sync(0xffffffffu, f));
        }
        if (lane == 0) cnts[warpId] = cnt;
    }
    __syncthreads();
    if (tid == 0) {
        int acc = 0;
        for (int c = 0; c < NCLS; c++) { bases[c] = acc; acc += cnts[c]; }
        for (int c = NCLS; c < 32; c++) { bases[c] = acc; cnts[c] = 0; }
    }
    __syncthreads();
    if (tid < 32) {
        g_base[b * 32 + tid] = bases[tid];
        g_cnt [b * 32 + tid] = cnts[tid];
    }

    if (warpId < NCLS) {
        const int base = bases[warpId];
        const float off = (float)warpId * m1v;
        int cnt = 0;
        for (int r0i = 0; r0i < NN; r0i += 32) {
            int r = r0i + lane;
            bool f = (clsR[r] == (unsigned char)warpId);
            unsigned bal = __ballot_sync(0xffffffffu, f);
            if (f) {
                int pos = b * NN + base + cnt + __popc(bal & ltmask);
                int idx = idxA[r];
                float4 bbx = bx4[idx];
                float x1 = bbx.x + off,           y1 = bbx.y + off;
                float x2 = (bbx.x + bbx.z) + off, y2 = (bbx.y + bbx.w) + off;
                g_obox[pos] = make_float4(x1, y1, x2, y2);
                g_boxc[pos] = bbx;                              // original xywh
                g_scc [pos] = __uint_as_float(~keysA[r]);       // exact score bits
                g_rank[pos] = (unsigned short)r;
            }
            cnt += __popc(bal);
        }
    }
    __syncthreads();
    // writes above are visible to PDL dependents after launch_dependents
    pdl_launch_dependents();
}

// ============================================================================
// K2: per-(batch,class) NMS + fused output writes. 512 threads / 16 warps.
//     PDL: blocks pre-launch while K1 drains; wait on grid dependency.
//     Phase A: warp-per-row pairwise masks via ballot (areas precomputed).
//     Phase B: kept-bit word-walk (exact greedy semantics).
// ============================================================================
__global__ __launch_bounds__(K2_THREADS) void k2_nms_kernel(float* __restrict__ out)
{
    __shared__ float4   sbox[MAXC];
    __shared__ float    sarea[MAXC];
    __shared__ unsigned sup[MAXC][MWORDS];
    __shared__ unsigned keepw[MWORDS];

    const int blk = blockIdx.x;
    const int b = blk / NCLS, c = blk % NCLS;
    const int tid  = threadIdx.x;
    const int lane = tid & 31;
    const int wId  = tid >> 5;

    // wait for K1's grid (PDL); all preamble above is independent of its data
    pdl_wait();

    const int base   = g_base[b * 32 + c];
    const int n_full = g_cnt [b * 32 + c];
    if (n_full <= 0) return;
    const int n = n_full > MAXC ? MAXC : n_full;   // unreachable clamp
    const int nw = (n + 31) >> 5;

    const int gbase = b * NN + base;

    for (int j = tid; j < n; j += K2_THREADS) {
        float4 bb = g_obox[gbase + j];
        sbox[j]  = bb;
        sarea[j] = (bb.z - bb.x) * (bb.w - bb.y);
    }
    __syncthreads();

    // ---- Phase A: warp per row i; lanes cover k-chunks >= (i+1)>>5; ballot
    for (int i = wId; i < n; i += K2_WARPS) {
        const float4 bi = sbox[i];
        const float areai = sarea[i];
        for (int cw = (i + 1) >> 5; cw < nw; cw++) {
            const int k = cw * 32 + lane;
            bool supbit = false;
            if (k > i && k < n) {
                float4 bk = sbox[k];
                float xx1 = fmaxf(bi.x, bk.x);
                float yy1 = fmaxf(bi.y, bk.y);
                float xx2 = fminf(bi.z, bk.z);
                float yy2 = fminf(bi.w, bk.w);
                float ww = fmaxf(xx2 - xx1, 0.0f);
                float hh = fmaxf(yy2 - yy1, 0.0f);
                float inter = ww * hh;
                float iou = inter / ((areai + sarea[k]) - inter);  // IEEE div: exact
                supbit = (iou > NMS_THR);
            }
            unsigned bal = __ballot_sync(0xffffffffu, supbit);
            if (lane == 0) sup[i][cw] = bal;
        }
    }
    __syncthreads();

    // ---- Phase B: warp 0; lane w owns keep-word w. Walk only KEPT bits.
    if (wId == 0) {
        unsigned kwreg = 0xffffffffu;
        for (int w = 0; w < nw; w++) {
            unsigned wcur = __shfl_sync(0xffffffffu, kwreg, w);
            while (wcur) {
                const int bit = __ffs(wcur) - 1;
                const int i = w * 32 + bit;
                if (i >= n) break;                 // only trailing OOB bits remain
                unsigned srow = (lane >= ((i + 1) >> 5) && lane < nw)
                                  ? sup[i][lane] : 0u;
                kwreg &= ~srow;
                unsigned sw = sup[i][w];           // broadcast LDS (uniform addr)
                wcur &= ~sw;                       // in-word suppressions
                wcur &= ~(1u << bit);              // mark processed (stays kept)
            }
        }
        if (lane < nw) keepw[lane] = kwreg;
    }
    __syncthreads();

    // ---- fused gather: final outputs (independent loads)
    const size_t outBoxesBase  = (size_t)BB * NN * NCLS + (size_t)BB * NN * 4;  // 819200
    const size_t outScoresBase = outBoxesBase + (size_t)BB * NN * 4;            // 950272
    const size_t outClsBase    = outScoresBase + (size_t)BB * NN;               // 983040
    const size_t outKeepBase   = outClsBase + (size_t)BB * NN;                  // 1015808

    const float cf = (float)c;
    for (int k = tid; k < n_full; k += K2_THREADS) {
        const int r = g_rank[gbase + k];
        const int g = b * NN + r;
        const unsigned kwv = keepw[k >> 5];
        const bool kp = (k < MAXC) && ((kwv >> (k & 31)) & 1u);
        const float4 bbx = g_boxc[gbase + k];
        const float scv = g_scc[gbase + k];

        float x1 = bbx.x, y1 = bbx.y;
        float x2 = bbx.x + bbx.z, y2 = bbx.y + bbx.w;
        float wo = x2 - x1, ho = y2 - y1;   // reference xywh->xyxy->xywh round trip

        ((float4*)(out + outBoxesBase))[g] =
            kp ? make_float4(x1, y1, wo, ho) : make_float4(0.f, 0.f, 0.f, 0.f);
        out[outScoresBase + g] = kp ? scv : 0.0f;
        out[outClsBase    + g] = kp ? cf : -1.0f;
        out[outKeepBase   + g] = kp ? 1.0f : 0.0f;
    }
}

extern "C" void kernel_launch(void* const* d_in, const int* in_sizes, int n_in,
                              void* d_out, int out_size) {
    const float* enc_cls = (const float*)d_in[0];
    const float* enc_reg = (const float*)d_in[1];
    const float* boxes   = (const float*)d_in[2];
    const float* scores  = (const float*)d_in[3];
    const int*   classes = (const int*)d_in[4];
    float* out = (float*)d_out;

    cudaFuncSetAttribute(k1_sort_kernel,
                         cudaFuncAttributeMaxDynamicSharedMemorySize, SMEM_BYTES);

    k1_sort_kernel<<<148, NTHREADS, SMEM_BYTES>>>(enc_cls, enc_reg, boxes, scores,
                                                  classes, out);

    // K2 with programmatic dependent launch: starts the instant K1's grid
    // signals launch_dependents (no host-side launch gap).
    cudaLaunchConfig_t cfg = {};
    cfg.gridDim  = dim3(BB * NCLS, 1, 1);
    cfg.blockDim = dim3(K2_THREADS, 1, 1);
    cfg.dynamicSmemBytes = 0;
    cfg.stream = 0;
    cudaLaunchAttribute attrs[1];
    attrs[0].id = cudaLaunchAttributeProgrammaticStreamSerialization;
    attrs[0].val.programmaticStreamSerializationAllowed = 1;
    cfg.attrs = attrs;
    cfg.numAttrs = 1;
    cudaLaunchKernelEx(&cfg, k2_nms_kernel, out);
}

// round 14
// speedup vs baseline: 1.1596x; 1.1596x over previous
#include <cuda_runtime.h>
#include <cstdint>

#define BB 16
#define NN 2048
#define NCLS 21
#define NTHREADS 1024
#define NMS_THR 0.3f

#define MAXC 384          // max boxes per class (mean ~98; huge safety margin)
#define MWORDS 12         // 384 bits of suppression mask per row
#define K2_THREADS 512
#define K2_WARPS 16

// ---- global scratch (static __device__; no allocation) ----
__device__ float4         g_obox[BB * NN];   // class-compacted offset xyxy
__device__ unsigned short g_rank[BB * NN];   // sorted-rank per compacted entry
__device__ unsigned short g_idx [BB * NN];   // original index per sorted rank
__device__ int            g_base[BB * 32];
__device__ int            g_cnt [BB * 32];

// ---- K1 dynamic shared memory layout (bytes) ----
#define OFF_KEYSA  0        // uint  [2048]   8192
#define OFF_KEYSB  8192     // uint  [2048]   8192
#define OFF_HIST   16384    // ushort[256*64] 32768   (hist[d*64+v])
#define OFF_IDXA   49152    // ushort[2048]   4096
#define OFF_IDXB   53248    // ushort[2048]   4096
#define OFF_CLS    57344    // uchar [2048]   2048
#define OFF_DTOT   59392    // uint  [256]    1024
#define OFF_BASES  60416    // int   [64]      256
#define OFF_MAXB   60672    // int               4
#define SMEM_BYTES 61440

// ============================================================================
// K1: per-batch stable sort by descending score + per-class compaction + copies
// (byte-identical to the proven fastest R6 version)
// ============================================================================
__global__ __launch_bounds__(NTHREADS) void k1_sort_kernel(
    const float* __restrict__ enc_cls,
    const float* __restrict__ enc_reg,
    const float* __restrict__ boxes,
    const float* __restrict__ scores,
    const int*   __restrict__ classes,
    float* __restrict__ out)
{
    const int tid = threadIdx.x;

    if (blockIdx.x >= BB) {
        // ---- copy blocks: pass-through of encoded_cls/encoded_reg
        const int cb  = blockIdx.x - BB;
        const int ncb = gridDim.x - BB;
        const int nClsV = (BB * NN * NCLS) / 4;
        const int nRegV = (BB * NN * 4) / 4;
        const float4* s1 = (const float4*)enc_cls;
        const float4* s2 = (const float4*)enc_reg;
        float4* d1 = (float4*)out;
        float4* d2 = (float4*)(out + (size_t)BB * NN * NCLS);
        for (int i = cb * NTHREADS + tid; i < nClsV; i += ncb * NTHREADS) d1[i] = s1[i];
        for (int i = cb * NTHREADS + tid; i < nRegV; i += ncb * NTHREADS) d2[i] = s2[i];
        return;
    }

    extern __shared__ char smem[];
    unsigned*       keysA = (unsigned*)      (smem + OFF_KEYSA);
    unsigned*       keysB = (unsigned*)      (smem + OFF_KEYSB);
    unsigned short* hist  = (unsigned short*)(smem + OFF_HIST);
    unsigned short* idxA  = (unsigned short*)(smem + OFF_IDXA);
    unsigned short* idxB  = (unsigned short*)(smem + OFF_IDXB);
    unsigned char*  clsR  = (unsigned char*) (smem + OFF_CLS);
    unsigned*       dtot  = (unsigned*)      (smem + OFF_DTOT);
    int*            cnts  = (int*)           (smem + OFF_BASES);
    int*            bases = (int*)           (smem + OFF_BASES) + 32;
    int*            maxb  = (int*)           (smem + OFF_MAXB);

    const int b = blockIdx.x;
    const float4* bx4 = (const float4*)(boxes + (size_t)b * NN * 4);
    const float*  sc  = scores  + (size_t)b * NN;
    const int*    cl  = classes + (size_t)b * NN;

    const int lane   = tid & 31;
    const int warpId = tid >> 5;
    const unsigned ltmask = (1u << lane) - 1u;

    if (tid == 0) *maxb = 0;
    __syncthreads();

    // ---- 1) keys (descending score, stable) + max coord reduce
    int localmax = 0;
    #pragma unroll
    for (int e = tid; e < NN; e += NTHREADS) {
        keysA[e] = ~__float_as_uint(sc[e]);
        idxA[e]  = (unsigned short)e;
        float4 bbx = bx4[e];
        float x2 = bbx.x + bbx.z, y2 = bbx.y + bbx.w;
        float m = fmaxf(fmaxf(bbx.x, bbx.y), fmaxf(x2, y2));
        localmax = max(localmax, __float_as_int(m));
    }
    atomicMax(maxb, localmax);
    __syncthreads();

    // ---- 2) stable LSD radix: 4 x 8-bit, 64 warp-chunks of 32
    const int v0 = warpId, v1 = warpId + 32;
    #pragma unroll
    for (int pass = 0; pass < 4; pass++) {
        const unsigned sh = pass * 8;
        const unsigned*       kin  = (pass & 1) ? keysB : keysA;
        unsigned*             kout = (pass & 1) ? keysA : keysB;
        const unsigned short* iin  = (pass & 1) ? idxB  : idxA;
        unsigned short*       iout = (pass & 1) ? idxA  : idxB;

        {   // zero hist (256*64 ushort = 2048 uint4)
            uint4* h4 = (uint4*)hist;
            #pragma unroll
            for (int i = tid; i < 2048; i += NTHREADS) h4[i] = make_uint4(0, 0, 0, 0);
        }
        __syncthreads();

        unsigned k0 = kin[tid], k1 = kin[tid + 1024];
        unsigned d0 = (k0 >> sh) & 255u, d1 = (k1 >> sh) & 255u;
        unsigned m0 = __match_any_sync(0xffffffffu, d0);
        unsigned r0 = __popc(m0 & ltmask);
        if (r0 == 0) hist[d0 * 64 + v0] = (unsigned short)__popc(m0);
        unsigned m1 = __match_any_sync(0xffffffffu, d1);
        unsigned r1 = __popc(m1 & ltmask);
        if (r1 == 0) hist[d1 * 64 + v1] = (unsigned short)__popc(m1);
        __syncthreads();

        // per-digit exclusive scan over 64 chunks: warp w scans digits [8w,8w+8)
        #pragma unroll
        for (int j = 0; j < 8; j++) {
            const int d = warpId * 8 + j;
            unsigned a  = hist[d * 64 + 2 * lane];
            unsigned b2 = hist[d * 64 + 2 * lane + 1];
            unsigned s = a + b2;
            unsigned incl = s;
            #pragma unroll
            for (int o = 1; o < 32; o <<= 1) {
                unsigned t = __shfl_up_sync(0xffffffffu, incl, o);
                if (lane >= o) incl += t;
            }
            unsigned excl = incl - s;
            hist[d * 64 + 2 * lane]     = (unsigned short)excl;
            hist[d * 64 + 2 * lane + 1] = (unsigned short)(excl + a);
            if (lane == 31) dtot[d] = incl;
        }
        __syncthreads();

        // exclusive scan of 256 digit totals (warp 0, 8 per lane)
        if (tid < 32) {
            unsigned s[8], lsum = 0;
            #pragma unroll
            for (int j = 0; j < 8; j++) { s[j] = dtot[tid * 8 + j]; lsum += s[j]; }
            unsigned tot = lsum;
            #pragma unroll
            for (int o = 1; o < 32; o <<= 1) {
                unsigned t = __shfl_up_sync(0xffffffffu, lsum, o);
                if (lane >= o) lsum += t;
            }
            unsigned run = lsum - tot;
            #pragma unroll
            for (int j = 0; j < 8; j++) { unsigned t = s[j]; dtot[tid * 8 + j] = run; run += t; }
        }
        __syncthreads();

        unsigned dst0 = dtot[d0] + hist[d0 * 64 + v0] + r0;
        kout[dst0] = k0; iout[dst0] = iin[tid];
        unsigned dst1 = dtot[d1] + hist[d1 * 64 + v1] + r1;
        kout[dst1] = k1; iout[dst1] = iin[tid + 1024];
        __syncthreads();
    }

    // ---- 3) classes by sorted rank; export sorted order
    #pragma unroll
    for (int r = tid; r < NN; r += NTHREADS) {
        unsigned short idx = idxA[r];
        clsR[r] = (unsigned char)cl[idx];
        g_idx[b * NN + r] = idx;
    }
    __syncthreads();

    // ---- 4) per-class compaction -> global (warp c owns class c)
    const float m1v = __int_as_float(*maxb) + 1.0f;

    if (warpId < NCLS) {
        int cnt = 0;
        for (int r0i = 0; r0i < NN; r0i += 32) {
            bool f = (clsR[r0i + lane] == (unsigned char)warpId);
            cnt += __popc(__ballot_sync(0xffffffffu, f));
        }
        if (lane == 0) cnts[warpId] = cnt;
    }
    __syncthreads();
    if (tid == 0) {
        int acc = 0;
        for (int c = 0; c < NCLS; c++) { bases[c] = acc; acc += cnts[c]; }
        for (int c = NCLS; c < 32; c++) { bases[c] = acc; cnts[c] = 0; }
    }
    __syncthreads();
    if (tid < 32) {
        g_base[b * 32 + tid] = bases[tid];
        g_cnt [b * 32 + tid] = cnts[tid];
    }

    if (warpId < NCLS) {
        const int base = bases[warpId];
        const float off = (float)warpId * m1v;
        int cnt = 0;
        for (int r0i = 0; r0i < NN; r0i += 32) {
            int r = r0i + lane;
            bool f = (clsR[r] == (unsigned char)warpId);
            unsigned bal = __ballot_sync(0xffffffffu, f);
            if (f) {
                int pos = base + cnt + __popc(bal & ltmask);
                int idx = idxA[r];
                float4 bbx = bx4[idx];
                float x1 = bbx.x + off,           y1 = bbx.y + off;
                float x2 = (bbx.x + bbx.z) + off, y2 = (bbx.y + bbx.w) + off;
                g_obox[b * NN + pos] = make_float4(x1, y1, x2, y2);
                g_rank[b * NN + pos] = (unsigned short)r;
            }
            cnt += __popc(bal);
        }
    }
}

// ============================================================================
// K2: per-(batch,class) NMS + fused output writes. 512 threads / 16 warps.
//     Phase A: warp-per-row pairwise masks via ballot (areas precomputed).
//     Phase B: kept-bit word-walk (R12-proven, exact greedy semantics).
//     Gather via g_rank -> g_idx -> boxes/scores (R6-proven path).
// ============================================================================
__global__ __launch_bounds__(K2_THREADS) void k2_nms_kernel(
    const float* __restrict__ boxes,
    const float* __restrict__ scores,
    float* __restrict__ out)
{
    __shared__ float4   sbox[MAXC];
    __shared__ float    sarea[MAXC];
    __shared__ unsigned sup[MAXC][MWORDS];
    __shared__ unsigned keepw[MWORDS];

    const int blk = blockIdx.x;
    const int b = blk / NCLS, c = blk % NCLS;
    const int tid  = threadIdx.x;
    const int lane = tid & 31;
    const int wId  = tid >> 5;

    const int base   = g_base[b * 32 + c];
    const int n_full = g_cnt [b * 32 + c];
    if (n_full <= 0) return;
    const int n = n_full > MAXC ? MAXC : n_full;   // unreachable clamp
    const int nw = (n + 31) >> 5;

    const int b2048 = b * NN;
    const int gbase = b2048 + base;

    for (int j = tid; j < n; j += K2_THREADS) {
        float4 bb = g_obox[gbase + j];
        sbox[j]  = bb;
        sarea[j] = (bb.z - bb.x) * (bb.w - bb.y);
    }
    __syncthreads();

    // ---- Phase A: warp per row i; lanes cover k-chunks >= (i+1)>>5; ballot
    for (int i = wId; i < n; i += K2_WARPS) {
        const float4 bi = sbox[i];
        const float areai = sarea[i];
        for (int cw = (i + 1) >> 5; cw < nw; cw++) {
            const int k = cw * 32 + lane;
            bool supbit = false;
            if (k > i && k < n) {
                float4 bk = sbox[k];
                float xx1 = fmaxf(bi.x, bk.x);
                float yy1 = fmaxf(bi.y, bk.y);
                float xx2 = fminf(bi.z, bk.z);
                float yy2 = fminf(bi.w, bk.w);
                float ww = fmaxf(xx2 - xx1, 0.0f);
                float hh = fmaxf(yy2 - yy1, 0.0f);
                float inter = ww * hh;
                float iou = inter / ((areai + sarea[k]) - inter);  // IEEE div: exact
                supbit = (iou > NMS_THR);
            }
            unsigned bal = __ballot_sync(0xffffffffu, supbit);
            if (lane == 0) sup[i][cw] = bal;
        }
    }
    __syncthreads();

    // ---- Phase B: warp 0; lane w owns keep-word w. Walk only KEPT bits.
    // wcur (warp-uniform) = "kept and not yet processed" mask of the current
    // word; suppression rows carry only k>i bits, so processed bits are never
    // re-set and words < current are final.
    if (wId == 0) {
        unsigned kwreg = 0xffffffffu;
        for (int w = 0; w < nw; w++) {
            unsigned wcur = __shfl_sync(0xffffffffu, kwreg, w);
            while (wcur) {
                const int bit = __ffs(wcur) - 1;
                const int i = w * 32 + bit;
                if (i >= n) break;                 // only trailing OOB bits remain
                unsigned srow = (lane >= ((i + 1) >> 5) && lane < nw)
                                  ? sup[i][lane] : 0u;
                kwreg &= ~srow;
                unsigned sw = sup[i][w];           // broadcast LDS (uniform addr)
                wcur &= ~sw;                       // in-word suppressions
                wcur &= ~(1u << bit);              // mark processed (stays kept)
            }
        }
        if (lane < nw) keepw[lane] = kwreg;
    }
    __syncthreads();

    // ---- fused gather: final outputs for this block's ranks
    const size_t outBoxesBase  = (size_t)BB * NN * NCLS + (size_t)BB * NN * 4;  // 819200
    const size_t outScoresBase = outBoxesBase + (size_t)BB * NN * 4;            // 950272
    const size_t outClsBase    = outScoresBase + (size_t)BB * NN;               // 983040
    const size_t outKeepBase   = outClsBase + (size_t)BB * NN;                  // 1015808

    const float cf = (float)c;
    for (int k = tid; k < n_full; k += K2_THREADS) {
        const int r = g_rank[gbase + k];
        const int g = b2048 + r;
        const unsigned kwv = keepw[k >> 5];
        const bool kp = (k < MAXC) && ((kwv >> (k & 31)) & 1u);
        const int idx = g_idx[g];
        const float4 bbx = ((const float4*)(boxes + (size_t)b * NN * 4))[idx];
        const float scv = scores[(size_t)b * NN + idx];

        float x1 = bbx.x, y1 = bbx.y;
        float x2 = bbx.x + bbx.z, y2 = bbx.y + bbx.w;
        float wo = x2 - x1, ho = y2 - y1;   // reference xywh->xyxy->xywh round trip

        ((float4*)(out + outBoxesBase))[g] =
            kp ? make_float4(x1, y1, wo, ho) : make_float4(0.f, 0.f, 0.f, 0.f);
        out[outScoresBase + g] = kp ? scv : 0.0f;
        out[outClsBase    + g] = kp ? cf : -1.0f;
        out[outKeepBase   + g] = kp ? 1.0f : 0.0f;
    }
}

extern "C" void kernel_launch(void* const* d_in, const int* in_sizes, int n_in,
                              void* d_out, int out_size) {
    const float* enc_cls = (const float*)d_in[0];
    const float* enc_reg = (const float*)d_in[1];
    const float* boxes   = (const float*)d_in[2];
    const float* scores  = (const float*)d_in[3];
    const int*   classes = (const int*)d_in[4];
    float* out = (float*)d_out;

    cudaFuncSetAttribute(k1_sort_kernel,
                         cudaFuncAttributeMaxDynamicSharedMemorySize, SMEM_BYTES);

    k1_sort_kernel<<<148, NTHREADS, SMEM_BYTES>>>(enc_cls, enc_reg, boxes, scores,
                                                  classes, out);
    k2_nms_kernel<<<BB * NCLS, K2_THREADS>>>(boxes, scores, out);
}

// round 17
// speedup vs baseline: 1.2531x; 1.0806x over previous
#include <cuda_runtime.h>
#include <cstdint>

#define BB 16
#define NN 2048
#define NCLS 21
#define NTHREADS 1024
#define NMS_THR 0.3f

#define MAXC 384          // max boxes per class (mean ~98; huge safety margin)
#define MWORDS 12         // 384 bits of suppression mask per row
#define K2_THREADS 512
#define K2_WARPS 16

// ---- global scratch (static __device__; no allocation) ----
__device__ float4         g_obox[BB * NN];   // class-compacted offset xyxy
__device__ unsigned short g_rank[BB * NN];   // sorted-rank per compacted entry
__device__ unsigned short g_idx [BB * NN];   // original index per sorted rank
__device__ int            g_base[BB * 32];
__device__ int            g_cnt [BB * 32];

// ---- K1 dynamic shared memory layout (bytes) ----
#define OFF_KEYSA  0        // uint  [2048]   8192
#define OFF_KEYSB  8192     // uint  [2048]   8192
#define OFF_HIST   16384    // ushort[256*64] 32768   (hist[d*64+v])
#define OFF_IDXA   49152    // ushort[2048]   4096
#define OFF_IDXB   53248    // ushort[2048]   4096
#define OFF_CLS    57344    // uchar [2048]   2048
#define OFF_DTOT   59392    // uint  [256]    1024
#define OFF_BASES  60416    // int   [64]      256
#define OFF_MAXB   60672    // int               4
#define SMEM_BYTES 61440

// ============================================================================
// K1: per-batch stable sort by descending score + parallel class compaction
//     (class compaction = one 21-bin stable radix-style pass, replacing the
//      two 64-iteration warp-serial loops)
// ============================================================================
__global__ __launch_bounds__(NTHREADS) void k1_sort_kernel(
    const float* __restrict__ enc_cls,
    const float* __restrict__ enc_reg,
    const float* __restrict__ boxes,
    const float* __restrict__ scores,
    const int*   __restrict__ classes,
    float* __restrict__ out)
{
    const int tid = threadIdx.x;

    if (blockIdx.x >= BB) {
        // ---- copy blocks: pass-through of encoded_cls/encoded_reg
        const int cb  = blockIdx.x - BB;
        const int ncb = gridDim.x - BB;
        const int nClsV = (BB * NN * NCLS) / 4;
        const int nRegV = (BB * NN * 4) / 4;
        const float4* s1 = (const float4*)enc_cls;
        const float4* s2 = (const float4*)enc_reg;
        float4* d1 = (float4*)out;
        float4* d2 = (float4*)(out + (size_t)BB * NN * NCLS);
        for (int i = cb * NTHREADS + tid; i < nClsV; i += ncb * NTHREADS) d1[i] = s1[i];
        for (int i = cb * NTHREADS + tid; i < nRegV; i += ncb * NTHREADS) d2[i] = s2[i];
        return;
    }

    extern __shared__ char smem[];
    unsigned*       keysA = (unsigned*)      (smem + OFF_KEYSA);
    unsigned*       keysB = (unsigned*)      (smem + OFF_KEYSB);
    unsigned short* hist  = (unsigned short*)(smem + OFF_HIST);
    unsigned short* idxA  = (unsigned short*)(smem + OFF_IDXA);
    unsigned short* idxB  = (unsigned short*)(smem + OFF_IDXB);
    unsigned char*  clsR  = (unsigned char*) (smem + OFF_CLS);
    unsigned*       dtot  = (unsigned*)      (smem + OFF_DTOT);
    int*            cnts  = (int*)           (smem + OFF_BASES);
    int*            bases = (int*)           (smem + OFF_BASES) + 32;
    int*            maxb  = (int*)           (smem + OFF_MAXB);

    const int b = blockIdx.x;
    const float4* bx4 = (const float4*)(boxes + (size_t)b * NN * 4);
    const float*  sc  = scores  + (size_t)b * NN;
    const int*    cl  = classes + (size_t)b * NN;

    const int lane   = tid & 31;
    const int warpId = tid >> 5;
    const unsigned ltmask = (1u << lane) - 1u;

    if (tid == 0) *maxb = 0;
    __syncthreads();

    // ---- 1) keys (descending score, stable) + max coord reduce
    int localmax = 0;
    #pragma unroll
    for (int e = tid; e < NN; e += NTHREADS) {
        keysA[e] = ~__float_as_uint(sc[e]);
        idxA[e]  = (unsigned short)e;
        float4 bbx = bx4[e];
        float x2 = bbx.x + bbx.z, y2 = bbx.y + bbx.w;
        float m = fmaxf(fmaxf(bbx.x, bbx.y), fmaxf(x2, y2));
        localmax = max(localmax, __float_as_int(m));
    }
    atomicMax(maxb, localmax);
    __syncthreads();

    // ---- 2) stable LSD radix: 4 x 8-bit, 64 warp-chunks of 32
    const int v0 = warpId, v1 = warpId + 32;
    #pragma unroll
    for (int pass = 0; pass < 4; pass++) {
        const unsigned sh = pass * 8;
        const unsigned*       kin  = (pass & 1) ? keysB : keysA;
        unsigned*             kout = (pass & 1) ? keysA : keysB;
        const unsigned short* iin  = (pass & 1) ? idxB  : idxA;
        unsigned short*       iout = (pass & 1) ? idxA  : idxB;

        {   // zero hist (256*64 ushort = 2048 uint4)
            uint4* h4 = (uint4*)hist;
            #pragma unroll
            for (int i = tid; i < 2048; i += NTHREADS) h4[i] = make_uint4(0, 0, 0, 0);
        }
        __syncthreads();

        unsigned k0 = kin[tid], k1 = kin[tid + 1024];
        unsigned d0 = (k0 >> sh) & 255u, d1 = (k1 >> sh) & 255u;
        unsigned m0 = __match_any_sync(0xffffffffu, d0);
        unsigned r0 = __popc(m0 & ltmask);
        if (r0 == 0) hist[d0 * 64 + v0] = (unsigned short)__popc(m0);
        unsigned m1 = __match_any_sync(0xffffffffu, d1);
        unsigned r1 = __popc(m1 & ltmask);
        if (r1 == 0) hist[d1 * 64 + v1] = (unsigned short)__popc(m1);
        __syncthreads();

        // per-digit exclusive scan over 64 chunks: warp w scans digits [8w,8w+8)
        #pragma unroll
        for (int j = 0; j < 8; j++) {
            const int d = warpId * 8 + j;
            unsigned a  = hist[d * 64 + 2 * lane];
            unsigned b2 = hist[d * 64 + 2 * lane + 1];
            unsigned s = a + b2;
            unsigned incl = s;
            #pragma unroll
            for (int o = 1; o < 32; o <<= 1) {
                unsigned t = __shfl_up_sync(0xffffffffu, incl, o);
                if (lane >= o) incl += t;
            }
            unsigned excl = incl - s;
            hist[d * 64 + 2 * lane]     = (unsigned short)excl;
            hist[d * 64 + 2 * lane + 1] = (unsigned short)(excl + a);
            if (lane == 31) dtot[d] = incl;
        }
        __syncthreads();

        // exclusive scan of 256 digit totals (warp 0, 8 per lane)
        if (tid < 32) {
            unsigned s[8], lsum = 0;
            #pragma unroll
            for (int j = 0; j < 8; j++) { s[j] = dtot[tid * 8 + j]; lsum += s[j]; }
            unsigned tot = lsum;
            #pragma unroll
            for (int o = 1; o < 32; o <<= 1) {
                unsigned t = __shfl_up_sync(0xffffffffu, lsum, o);
                if (lane >= o) lsum += t;
            }
            unsigned run = lsum - tot;
            #pragma unroll
            for (int j = 0; j < 8; j++) { unsigned t = s[j]; dtot[tid * 8 + j] = run; run += t; }
        }
        __syncthreads();

        unsigned dst0 = dtot[d0] + hist[d0 * 64 + v0] + r0;
        kout[dst0] = k0; iout[dst0] = iin[tid];
        unsigned dst1 = dtot[d1] + hist[d1 * 64 + v1] + r1;
        kout[dst1] = k1; iout[dst1] = iin[tid + 1024];
        __syncthreads();
    }
    // final order in idxA

    // ---- 3) classes by sorted rank; export sorted order
    #pragma unroll
    for (int r = tid; r < NN; r += NTHREADS) {
        unsigned short idx = idxA[r];
        clsR[r] = (unsigned char)cl[idx];
        g_idx[b * NN + r] = idx;
    }
    __syncthreads();

    // ---- 4) class compaction as ONE 21-bin stable radix-style pass
    // zero cls-hist region (21*64 ushort = 2688 B = 168 uint4)
    {
        uint4* h4 = (uint4*)hist;
        if (tid < 168) h4[tid] = make_uint4(0, 0, 0, 0);
    }
    __syncthreads();

    // per-chunk per-class histogram via match_any (2 elements/thread)
    const unsigned c0 = clsR[tid];
    const unsigned c1 = clsR[tid + 1024];
    unsigned cm0 = __match_any_sync(0xffffffffu, c0);
    unsigned crk0 = __popc(cm0 & ltmask);
    if (crk0 == 0) hist[c0 * 64 + v0] = (unsigned short)__popc(cm0);
    unsigned cm1 = __match_any_sync(0xffffffffu, c1);
    unsigned crk1 = __popc(cm1 & ltmask);
    if (crk1 == 0) hist[c1 * 64 + v1] = (unsigned short)__popc(cm1);
    __syncthreads();

    // per-class exclusive scan over 64 chunks (warps 0..20, one class each)
    if (warpId < NCLS) {
        const int d = warpId;
        unsigned a  = hist[d * 64 + 2 * lane];
        unsigned b2 = hist[d * 64 + 2 * lane + 1];
        unsigned s = a + b2;
        unsigned incl = s;
        #pragma unroll
        for (int o = 1; o < 32; o <<= 1) {
            unsigned t = __shfl_up_sync(0xffffffffu, incl, o);
            if (lane >= o) incl += t;
        }
        unsigned excl = incl - s;
        hist[d * 64 + 2 * lane]     = (unsigned short)excl;
        hist[d * 64 + 2 * lane + 1] = (unsigned short)(excl + a);
        if (lane == 31) dtot[d] = incl;
    }
    __syncthreads();

    // exclusive scan of 21 class totals (warp 0); export g_base/g_cnt
    if (tid < 32) {
        unsigned v = (lane < NCLS) ? dtot[lane] : 0u;
        unsigned incl = v;
        #pragma unroll
        for (int o = 1; o < 32; o <<= 1) {
            unsigned t = __shfl_up_sync(0xffffffffu, incl, o);
            if (lane >= o) incl += t;
        }
        unsigned excl = incl - v;
        bases[lane] = (int)excl;
        cnts[lane]  = (int)v;
        g_base[b * 32 + lane] = (int)excl;
        g_cnt [b * 32 + lane] = (int)v;
    }
    __syncthreads();

    // scatter: each thread places its 2 elements (positions identical to the
    // old serial warp-per-class loop: chunk-major + within-chunk lane order)
    const float m1v = __int_as_float(*maxb) + 1.0f;
    {
        int pos0 = bases[c0] + hist[c0 * 64 + v0] + (int)crk0;
        int idx0 = idxA[tid];
        float4 bb0 = bx4[idx0];
        float off0 = (float)c0 * m1v;
        g_obox[b * NN + pos0] = make_float4(bb0.x + off0, bb0.y + off0,
                                            (bb0.x + bb0.z) + off0,
                                            (bb0.y + bb0.w) + off0);
        g_rank[b * NN + pos0] = (unsigned short)tid;

        int pos1 = bases[c1] + hist[c1 * 64 + v1] + (int)crk1;
        int idx1 = idxA[tid + 1024];
        float4 bb1 = bx4[idx1];
        float off1 = (float)c1 * m1v;
        g_obox[b * NN + pos1] = make_float4(bb1.x + off1, bb1.y + off1,
                                            (bb1.x + bb1.z) + off1,
                                            (bb1.y + bb1.w) + off1);
        g_rank[b * NN + pos1] = (unsigned short)(tid + 1024);
    }
}

// ============================================================================
// K2: per-(batch,class) NMS + fused output writes. 512 threads / 16 warps.
//     (byte-identical to the R14-proven 26.7us version)
// ============================================================================
__global__ __launch_bounds__(K2_THREADS) void k2_nms_kernel(
    const float* __restrict__ boxes,
    const float* __restrict__ scores,
    float* __restrict__ out)
{
    __shared__ float4   sbox[MAXC];
    __shared__ float    sarea[MAXC];
    __shared__ unsigned sup[MAXC][MWORDS];
    __shared__ unsigned keepw[MWORDS];

    const int blk = blockIdx.x;
    const int b = blk / NCLS, c = blk % NCLS;
    const int tid  = threadIdx.x;
    const int lane = tid & 31;
    const int wId  = tid >> 5;

    const int base   = g_base[b * 32 + c];
    const int n_full = g_cnt [b * 32 + c];
    if (n_full <= 0) return;
    const int n = n_full > MAXC ? MAXC : n_full;   // unreachable clamp
    const int nw = (n + 31) >> 5;

    const int b2048 = b * NN;
    const int gbase = b2048 + base;

    for (int j = tid; j < n; j += K2_THREADS) {
        float4 bb = g_obox[gbase + j];
        sbox[j]  = bb;
        sarea[j] = (bb.z - bb.x) * (bb.w - bb.y);
    }
    __syncthreads();

    // ---- Phase A: warp per row i; lanes cover k-chunks >= (i+1)>>5; ballot
    for (int i = wId; i < n; i += K2_WARPS) {
        const float4 bi = sbox[i];
        const float areai = sarea[i];
        for (int cw = (i + 1) >> 5; cw < nw; cw++) {
            const int k = cw * 32 + lane;
            bool supbit = false;
            if (k > i && k < n) {
                float4 bk = sbox[k];
                float xx1 = fmaxf(bi.x, bk.x);
                float yy1 = fmaxf(bi.y, bk.y);
                float xx2 = fminf(bi.z, bk.z);
                float yy2 = fminf(bi.w, bk.w);
                float ww = fmaxf(xx2 - xx1, 0.0f);
                float hh = fmaxf(yy2 - yy1, 0.0f);
                float inter = ww * hh;
                float iou = inter / ((areai + sarea[k]) - inter);  // IEEE div: exact
                supbit = (iou > NMS_THR);
            }
            unsigned bal = __ballot_sync(0xffffffffu, supbit);
            if (lane == 0) sup[i][cw] = bal;
        }
    }
    __syncthreads();

    // ---- Phase B: warp 0; lane w owns keep-word w. Walk only KEPT bits.
    if (wId == 0) {
        unsigned kwreg = 0xffffffffu;
        for (int w = 0; w < nw; w++) {
            unsigned wcur = __shfl_sync(0xffffffffu, kwreg, w);
            while (wcur) {
                const int bit = __ffs(wcur) - 1;
                const int i = w * 32 + bit;
                if (i >= n) break;                 // only trailing OOB bits remain
                unsigned srow = (lane >= ((i + 1) >> 5) && lane < nw)
                                  ? sup[i][lane] : 0u;
                kwreg &= ~srow;
                unsigned sw = sup[i][w];           // broadcast LDS (uniform addr)
                wcur &= ~sw;                       // in-word suppressions
                wcur &= ~(1u << bit);              // mark processed (stays kept)
            }
        }
        if (lane < nw) keepw[lane] = kwreg;
    }
    __syncthreads();

    // ---- fused gather: final outputs for this block's ranks
    const size_t outBoxesBase  = (size_t)BB * NN * NCLS + (size_t)BB * NN * 4;  // 819200
    const size_t outScoresBase = outBoxesBase + (size_t)BB * NN * 4;            // 950272
    const size_t outClsBase    = outScoresBase + (size_t)BB * NN;               // 983040
    const size_t outKeepBase   = outClsBase + (size_t)BB * NN;                  // 1015808

    const float cf = (float)c;
    for (int k = tid; k < n_full; k += K2_THREADS) {
        const int r = g_rank[gbase + k];
        const int g = b2048 + r;
        const unsigned kwv = keepw[k >> 5];
        const bool kp = (k < MAXC) && ((kwv >> (k & 31)) & 1u);
        const int idx = g_idx[g];
        const float4 bbx = ((const float4*)(boxes + (size_t)b * NN * 4))[idx];
        const float scv = scores[(size_t)b * NN + idx];

        float x1 = bbx.x, y1 = bbx.y;
        float x2 = bbx.x + bbx.z, y2 = bbx.y + bbx.w;
        float wo = x2 - x1, ho = y2 - y1;   // reference xywh->xyxy->xywh round trip

        ((float4*)(out + outBoxesBase))[g] =
            kp ? make_float4(x1, y1, wo, ho) : make_float4(0.f, 0.f, 0.f, 0.f);
        out[outScoresBase + g] = kp ? scv : 0.0f;
        out[outClsBase    + g] = kp ? cf : -1.0f;
        out[outKeepBase   + g] = kp ? 1.0f : 0.0f;
    }
}

extern "C" void kernel_launch(void* const* d_in, const int* in_sizes, int n_in,
                              void* d_out, int out_size) {
    const float* enc_cls = (const float*)d_in[0];
    const float* enc_reg = (const float*)d_in[1];
    const float* boxes   = (const float*)d_in[2];
    const float* scores  = (const float*)d_in[3];
    const int*   classes = (const int*)d_in[4];
    float* out = (float*)d_out;

    cudaFuncSetAttribute(k1_sort_kernel,
                         cudaFuncAttributeMaxDynamicSharedMemorySize, SMEM_BYTES);

    k1_sort_kernel<<<148, NTHREADS, SMEM_BYTES>>>(enc_cls, enc_reg, boxes, scores,
                                                  classes, out);
    k2_nms_kernel<<<BB * NCLS, K2_THREADS>>>(boxes, scores, out);
}